// round 16
// baseline (speedup 1.0000x reference)
#include <cuda_runtime.h>
#include <cuda_fp16.h>
#include <math.h>
#include <stdint.h>

#define NTOK 8192
#define DDIM 1024
#define NEXP 8
#define FDIM 3264
#define NROW (NEXP * NTOK)
#define EFD  (NEXP * FDIM * DDIM)

#define BM 128
#define BK 64                          // halves per k-strip
#define SSTR 72                        // smem row stride in halves (conflict-free)
#define TILE_B (128 * SSTR * 2)        // 18432 bytes per 128-row tile
#define TILE2B (256 * SSTR * 2)        // 36864 bytes per 256-row tile
#define ST1 4                          // gemm1 stages (A+G+U = 55296 B/stage)
#define ST2 3                          // gemm2 stages (A+B = 55296 B/stage)

// ---------------- device scratch ----------------
__device__ int    g_counts[NEXP];
__device__ int    g_pos[NTOK * 2];
__device__ int    g_tok[NROW];
__device__ float  g_wts[NROW];
__device__ __half g_Xe[(size_t)NROW * DDIM];
__device__ __half g_H [(size_t)NROW * FDIM];
__device__ __half g_W16[(size_t)3 * EFD];   // [gp | up | down] in fp16

// ---------------- helpers ----------------
__device__ __forceinline__ uint32_t smem_u32(const void* p) {
    uint32_t a;
    asm("{ .reg .u64 t; cvta.to.shared.u64 t, %1; cvt.u32.u64 %0, t; }" : "=r"(a) : "l"(p));
    return a;
}
__device__ __forceinline__ void cp16(uint32_t dst, const void* src, bool valid) {
    uint32_t sz = valid ? 16u : 0u;
    asm volatile("cp.async.cg.shared.global [%0], [%1], 16, %2;"
                 :: "r"(dst), "l"(src), "r"(sz));
}
__device__ __forceinline__ void cp_commit() {
    asm volatile("cp.async.commit_group;" ::: "memory");
}
__device__ __forceinline__ void cp_wait1() {
    asm volatile("cp.async.wait_group 1;" ::: "memory");
}
__device__ __forceinline__ void cp_wait2() {
    asm volatile("cp.async.wait_group 2;" ::: "memory");
}
__device__ __forceinline__ void mma16(float* c, const uint32_t* a, const uint32_t* b) {
    asm("mma.sync.aligned.m16n8k16.row.col.f32.f16.f16.f32 "
        "{%0,%1,%2,%3}, {%4,%5,%6,%7}, {%8,%9}, {%0,%1,%2,%3};"
        : "+f"(c[0]), "+f"(c[1]), "+f"(c[2]), "+f"(c[3])
        : "r"(a[0]), "r"(a[1]), "r"(a[2]), "r"(a[3]), "r"(b[0]), "r"(b[1]));
}
__device__ __forceinline__ void ldsm4(uint32_t* r, uint32_t addr) {
    asm volatile("ldmatrix.sync.aligned.m8n8.x4.shared.b16 {%0,%1,%2,%3}, [%4];"
                 : "=r"(r[0]), "=r"(r[1]), "=r"(r[2]), "=r"(r[3]) : "r"(addr));
}

// ============================================================
// init / conv / router / gather
// ============================================================
__global__ void init_kernel(float* __restrict__ out, int n) {
    int i = blockIdx.x * blockDim.x + threadIdx.x;
    if (i < NEXP) g_counts[i] = 0;
    if (i < n) out[i] = 0.f;
}

// convert gp+up for one expert-half (half = 0: experts 0-3, 1: experts 4-7)
__global__ __launch_bounds__(256) void convh_kernel(const float4* __restrict__ gsrc,
                                                    const float4* __restrict__ usrc,
                                                    int half) {
    const int n4 = EFD / 8;                 // float4 elems per half tensor
    const float4* src = (blockIdx.y ? usrc : gsrc) + (size_t)half * n4;
    uint2* dst = (uint2*)g_W16 + (size_t)blockIdx.y * (EFD / 4) + (size_t)half * n4;
    int stride = gridDim.x * blockDim.x;
    for (int i = blockIdx.x * blockDim.x + threadIdx.x; i < n4; i += stride) {
        float4 v = src[i];
        __half2 h0 = __floats2half2_rn(v.x, v.y);
        __half2 h1 = __floats2half2_rn(v.z, v.w);
        uint2 o;
        o.x = *(const uint32_t*)&h0;
        o.y = *(const uint32_t*)&h1;
        dst[i] = o;
    }
}

// convert down_w
__global__ __launch_bounds__(256) void convd_kernel(const float4* __restrict__ dsrc) {
    const int n4 = EFD / 4;
    uint2* dst = (uint2*)g_W16 + 2 * (size_t)(EFD / 4);
    int stride = gridDim.x * blockDim.x;
    for (int i = blockIdx.x * blockDim.x + threadIdx.x; i < n4; i += stride) {
        float4 v = dsrc[i];
        __half2 h0 = __floats2half2_rn(v.x, v.y);
        __half2 h1 = __floats2half2_rn(v.z, v.w);
        uint2 o;
        o.x = *(const uint32_t*)&h0;
        o.y = *(const uint32_t*)&h1;
        dst[i] = o;
    }
}

__global__ void router_kernel(const float* __restrict__ x,
                              const float* __restrict__ gw,
                              const float* __restrict__ gb) {
    int warp = (blockIdx.x * blockDim.x + threadIdx.x) >> 5;
    int lane = threadIdx.x & 31;
    if (warp >= NTOK) return;
    const float4* xr = (const float4*)(x + (size_t)warp * DDIM);

    float acc[NEXP];
#pragma unroll
    for (int e = 0; e < NEXP; e++) acc[e] = 0.f;
#pragma unroll
    for (int k4 = 0; k4 < DDIM / 4 / 32; k4++) {      // 8 iterations, float4 each
        int k = k4 * 32 + lane;
        float4 xv = xr[k];
#pragma unroll
        for (int e = 0; e < NEXP; e++) {
            float4 wv = ((const float4*)(gw + e * DDIM))[k];
            acc[e] += xv.x * wv.x + xv.y * wv.y + xv.z * wv.z + xv.w * wv.w;
        }
    }
#pragma unroll
    for (int e = 0; e < NEXP; e++)
#pragma unroll
        for (int off = 16; off; off >>= 1)
            acc[e] += __shfl_xor_sync(0xffffffffu, acc[e], off);

    if (lane == 0) {
        float mx = -1e30f;
#pragma unroll
        for (int e = 0; e < NEXP; e++) { acc[e] += gb[e]; mx = fmaxf(mx, acc[e]); }
        float p[NEXP];
#pragma unroll
        for (int e = 0; e < NEXP; e++) p[e] = expf(acc[e] - mx);
        int i1 = 0; float v1 = p[0];
#pragma unroll
        for (int e = 1; e < NEXP; e++) if (p[e] > v1) { v1 = p[e]; i1 = e; }
        int i2 = -1; float v2 = -1.f;
#pragma unroll
        for (int e = 0; e < NEXP; e++) if (e != i1 && p[e] > v2) { v2 = p[e]; i2 = e; }
        float inv = 1.f / (v1 + v2);
        int s1 = atomicAdd(&g_counts[i1], 1);
        int s2 = atomicAdd(&g_counts[i2], 1);
        g_wts[i1 * NTOK + s1] = v1 * inv;
        g_wts[i2 * NTOK + s2] = v2 * inv;
        g_tok[i1 * NTOK + s1] = warp;
        g_tok[i2 * NTOK + s2] = warp;
        g_pos[2 * warp]     = i1 * NTOK + s1;
        g_pos[2 * warp + 1] = i2 * NTOK + s2;
    }
}

__global__ __launch_bounds__(256) void gather_kernel(const float* __restrict__ x) {
    int t  = blockIdx.x;
    int p0 = g_pos[2 * t], p1 = g_pos[2 * t + 1];
    float4 v = ((const float4*)(x + (size_t)t * DDIM))[threadIdx.x];
    __half2 h0 = __floats2half2_rn(v.x, v.y);
    __half2 h1 = __floats2half2_rn(v.z, v.w);
    uint2 o;
    o.x = *(const uint32_t*)&h0;
    o.y = *(const uint32_t*)&h1;
    ((uint2*)(g_Xe + (size_t)p0 * DDIM))[threadIdx.x] = o;
    ((uint2*)(g_Xe + (size_t)p1 * DDIM))[threadIdx.x] = o;
}

// ============================================================
// GEMM1: [128 slot] x [128 f], K=1024, G and U, silu -> g_H (fp16)
// 256 thr, 2x4 warp grid, warp tile 64x32, ldmatrix, 4 stages
// zbase selects expert range (expert = zbase + blockIdx.z)
// ============================================================
__global__ __launch_bounds__(256, 1) void gemm1_kernel(
    const float* __restrict__ gpb, const float* __restrict__ upb, int zbase) {

    int e   = zbase + blockIdx.z;
    int cnt = g_counts[e];
    int m0  = blockIdx.y * BM;
    if (m0 >= cnt) return;
    int n0  = blockIdx.x * 128;
    int ebase = e * NTOK;

    extern __shared__ __align__(16) __half sh[];
    uint32_t sbase = smem_u32(sh);

    int tid = threadIdx.x;
    int wid = tid >> 5, lane = tid & 31;
    int wr = wid >> 2, wc = wid & 3;        // 2 x 4 warp grid
    int g = lane >> 2, t = lane & 3;

    int rowA = wr * 64 + ((lane >> 3) & 1) * 8 + (lane & 7);
    int colA = ((lane >> 4) & 1) * 8;
    int aoff = rowA * SSTR + colA;
    int rowB = wc * 32 + ((lane >> 4) & 1) * 8 + (lane & 7);
    int colB = ((lane >> 3) & 1) * 8;
    int boff = rowB * SSTR + colB;

    const __half* srcA = g_Xe + (size_t)(ebase + m0) * DDIM;

    float cg[4][4][4], cu[4][4][4];
#pragma unroll
    for (int i = 0; i < 4; i++)
#pragma unroll
        for (int j = 0; j < 4; j++)
#pragma unroll
            for (int r = 0; r < 4; r++) { cg[i][j][r] = 0.f; cu[i][j][r] = 0.f; }

    const int KT = DDIM / BK;               // 16

    auto issue = [&](int kt, int st) {
        int k0 = kt * BK;
        uint32_t sA = sbase + st * (3 * TILE_B);
        uint32_t sG = sA + TILE_B;
        uint32_t sU = sG + TILE_B;
#pragma unroll
        for (int i = 0; i < 4; i++) {
            int c = i * 256 + tid;
            int row = c >> 3, kc = c & 7;
            uint32_t doff = (uint32_t)(row * SSTR + kc * 8) * 2;
            cp16(sA + doff, srcA + (size_t)row * DDIM + k0 + kc * 8, true);
            int nrow = n0 + row;
            bool ok = nrow < FDIM;
            int nr = ok ? nrow : (FDIM - 1);
            size_t woff = ((size_t)e * FDIM + nr) * DDIM + k0 + kc * 8;
            cp16(sG + doff, g_W16 + woff, ok);
            cp16(sU + doff, g_W16 + EFD + woff, ok);
        }
        cp_commit();
    };

#pragma unroll
    for (int s = 0; s < ST1 - 1; s++) issue(s, s);

    for (int kt = 0; kt < KT; kt++) {
        cp_wait2();
        __syncthreads();
        if (kt + ST1 - 1 < KT) issue(kt + ST1 - 1, (kt + ST1 - 1) % ST1);
        else cp_commit();

        int st = kt % ST1;
        uint32_t sA = sbase + st * (3 * TILE_B);
        uint32_t sG = sA + TILE_B;
        uint32_t sU = sG + TILE_B;

#pragma unroll
        for (int kk = 0; kk < 4; kk++) {
            int kb = kk * 16;
            uint32_t a[4][4];
#pragma unroll
            for (int mt = 0; mt < 4; mt++)
                ldsm4(a[mt], sA + (uint32_t)(aoff + mt * 16 * SSTR + kb) * 2);
            uint32_t bg[4][2], bu[4][2];
#pragma unroll
            for (int h = 0; h < 2; h++) {
                uint32_t r[4];
                ldsm4(r, sG + (uint32_t)(boff + h * 16 * SSTR + kb) * 2);
                bg[2*h][0] = r[0]; bg[2*h][1] = r[1];
                bg[2*h+1][0] = r[2]; bg[2*h+1][1] = r[3];
                ldsm4(r, sU + (uint32_t)(boff + h * 16 * SSTR + kb) * 2);
                bu[2*h][0] = r[0]; bu[2*h][1] = r[1];
                bu[2*h+1][0] = r[2]; bu[2*h+1][1] = r[3];
            }
#pragma unroll
            for (int mt = 0; mt < 4; mt++)
#pragma unroll
                for (int nt = 0; nt < 4; nt++) {
                    mma16(cg[mt][nt], a[mt], bg[nt]);
                    mma16(cu[mt][nt], a[mt], bu[nt]);
                }
        }
    }

    // ---- epilogue: silu(g*u) -> g_H (fp16) ----
#pragma unroll
    for (int mt = 0; mt < 4; mt++) {
        int mrow = wr * 64 + mt * 16 + g;
#pragma unroll
        for (int p = 0; p < 2; p++) {
            int slot = m0 + mrow + p * 8;
            bool live = slot < cnt;
            size_t hbase = ((size_t)ebase + slot) * FDIM;
#pragma unroll
            for (int nt = 0; nt < 4; nt++) {
                int col = n0 + wc * 32 + nt * 8 + 2 * t;
                if (live && col < FDIM) {
                    float2 gb = *(const float2*)(gpb + (size_t)e * FDIM + col);
                    float2 ub = *(const float2*)(upb + (size_t)e * FDIM + col);
                    float g0 = cg[mt][nt][2 * p + 0] + gb.x;
                    float g1 = cg[mt][nt][2 * p + 1] + gb.y;
                    float u0 = cu[mt][nt][2 * p + 0] + ub.x;
                    float u1 = cu[mt][nt][2 * p + 1] + ub.y;
                    float z0 = g0 * u0, z1 = g1 * u1;
                    float h0 = z0 / (1.f + expf(-z0));
                    float h1 = z1 / (1.f + expf(-z1));
                    *(__half2*)(g_H + hbase + col) = __floats2half2_rn(h0, h1);
                }
            }
        }
    }
}

// ============================================================
// GEMM2: [128 slot] x [256 d], K=3264 over g_H (fp16),
// 256 thr, 2x4 warp grid, warp tile 64x64, ldmatrix, 3 stages,
// weighted atomicAdd scatter into out
// ============================================================
__global__ __launch_bounds__(256, 1) void gemm2_kernel(
    const float* __restrict__ dwb, float* __restrict__ out) {

    int e   = blockIdx.z;
    int cnt = g_counts[e];
    int m0  = blockIdx.y * BM;
    if (m0 >= cnt) return;
    int n0  = blockIdx.x * 256;
    int ebase = e * NTOK;

    const __half* wd16 = g_W16 + 2 * (size_t)EFD;

    extern __shared__ __align__(16) __half sh[];
    uint32_t sbase = smem_u32(sh);

    int tid = threadIdx.x;
    int wid = tid >> 5, lane = tid & 31;
    int wr = wid >> 2, wc = wid & 3;        // 2 x 4 warp grid, warp tile 64x64
    int g = lane >> 2, t = lane & 3;

    int rowA = wr * 64 + ((lane >> 3) & 1) * 8 + (lane & 7);
    int colA = ((lane >> 4) & 1) * 8;
    int aoff = rowA * SSTR + colA;
    int rowB = wc * 64 + ((lane >> 4) & 1) * 8 + (lane & 7);
    int colB = ((lane >> 3) & 1) * 8;
    int boff = rowB * SSTR + colB;

    const __half* srcA = g_H + (size_t)(ebase + m0) * FDIM;

    float c[4][8][4];
#pragma unroll
    for (int i = 0; i < 4; i++)
#pragma unroll
        for (int j = 0; j < 8; j++)
#pragma unroll
            for (int r = 0; r < 4; r++) c[i][j][r] = 0.f;

    const int KT = FDIM / BK;               // 51
    const int STAGE_B = TILE_B + TILE2B;    // 55296

    auto issue = [&](int kt, int st) {
        int k0 = kt * BK;
        uint32_t sA = sbase + st * STAGE_B;
        uint32_t sB = sA + TILE_B;
#pragma unroll
        for (int i = 0; i < 4; i++) {
            int cc = i * 256 + tid;
            int row = cc >> 3, kc = cc & 7;
            uint32_t doff = (uint32_t)(row * SSTR + kc * 8) * 2;
            cp16(sA + doff, srcA + (size_t)row * FDIM + k0 + kc * 8, true);
        }
#pragma unroll
        for (int j = 0; j < 8; j++) {
            int cc = j * 256 + tid;
            int row = cc >> 3, kc = cc & 7;
            uint32_t doff = (uint32_t)(row * SSTR + kc * 8) * 2;
            cp16(sB + doff, wd16 + ((size_t)e * DDIM + n0 + row) * FDIM + k0 + kc * 8, true);
        }
        cp_commit();
    };

#pragma unroll
    for (int s = 0; s < ST2 - 1; s++) issue(s, s);

    for (int kt = 0; kt < KT; kt++) {
        cp_wait1();
        __syncthreads();
        if (kt + ST2 - 1 < KT) issue(kt + ST2 - 1, (kt + ST2 - 1) % ST2);
        else cp_commit();

        int st = kt % ST2;
        uint32_t sA = sbase + st * STAGE_B;
        uint32_t sB = sA + TILE_B;

#pragma unroll
        for (int kk = 0; kk < 4; kk++) {
            int kb = kk * 16;
            uint32_t a[4][4];
#pragma unroll
            for (int mt = 0; mt < 4; mt++)
                ldsm4(a[mt], sA + (uint32_t)(aoff + mt * 16 * SSTR + kb) * 2);
            uint32_t b[8][2];
#pragma unroll
            for (int h = 0; h < 4; h++) {
                uint32_t r[4];
                ldsm4(r, sB + (uint32_t)(boff + h * 16 * SSTR + kb) * 2);
                b[2*h][0] = r[0]; b[2*h][1] = r[1];
                b[2*h+1][0] = r[2]; b[2*h+1][1] = r[3];
            }
#pragma unroll
            for (int mt = 0; mt < 4; mt++)
#pragma unroll
                for (int nt = 0; nt < 8; nt++)
                    mma16(c[mt][nt], a[mt], b[nt]);
        }
    }

    // ---- epilogue: (c + bias) * w, atomicAdd scatter ----
#pragma unroll
    for (int mt = 0; mt < 4; mt++) {
        int mrow = wr * 64 + mt * 16 + g;
#pragma unroll
        for (int p = 0; p < 2; p++) {
            int slot = m0 + mrow + p * 8;
            if (slot >= cnt) continue;
            float w   = g_wts[ebase + slot];
            int   tok = g_tok[ebase + slot];
            float* orow = out + (size_t)tok * DDIM;
#pragma unroll
            for (int nt = 0; nt < 8; nt++) {
                int col = n0 + wc * 64 + nt * 8 + 2 * t;
                float2 db = *(const float2*)(dwb + (size_t)e * DDIM + col);
                float y0 = (c[mt][nt][2 * p + 0] + db.x) * w;
                float y1 = (c[mt][nt][2 * p + 1] + db.y) * w;
                atomicAdd(orow + col, y0);
                atomicAdd(orow + col + 1, y1);
            }
        }
    }
}

// ============================================================
extern "C" void kernel_launch(void* const* d_in, const int* in_sizes, int n_in,
                              void* d_out, int out_size) {
    const float* x      = (const float*)d_in[0];
    const float* gate_w = (const float*)d_in[1];
    const float* gate_b = (const float*)d_in[2];
    const float* up_w   = (const float*)d_in[3];
    const float* up_b   = (const float*)d_in[4];
    const float* gp_w   = (const float*)d_in[5];
    const float* gp_b   = (const float*)d_in[6];
    const float* down_w = (const float*)d_in[7];
    const float* down_b = (const float*)d_in[8];
    float* out = (float*)d_out;
    (void)in_sizes; (void)n_in;

    // one-time host-side setup (no device allocations)
    static cudaStream_t s_side = nullptr;
    static cudaEvent_t e_fork = nullptr, e_a = nullptr, e_b = nullptr, e_c2 = nullptr;
    if (!s_side) {
        cudaStreamCreateWithFlags(&s_side, cudaStreamNonBlocking);
        cudaEventCreateWithFlags(&e_fork, cudaEventDisableTiming);
        cudaEventCreateWithFlags(&e_a,    cudaEventDisableTiming);
        cudaEventCreateWithFlags(&e_b,    cudaEventDisableTiming);
        cudaEventCreateWithFlags(&e_c2,   cudaEventDisableTiming);
        cudaFuncSetAttribute(gemm1_kernel, cudaFuncAttributeMaxDynamicSharedMemorySize,
                             ST1 * 3 * TILE_B);
        cudaFuncSetAttribute(gemm2_kernel, cudaFuncAttributeMaxDynamicSharedMemorySize,
                             ST2 * (TILE_B + TILE2B));
    }

    // ---- fork: weight conversion on side stream, expert-half pipelined ----
    cudaEventRecord(e_fork, 0);
    cudaStreamWaitEvent(s_side, e_fork, 0);

    dim3 gch(1024, 2);
    convh_kernel<<<gch, 256, 0, s_side>>>((const float4*)gp_w, (const float4*)up_w, 0);
    cudaEventRecord(e_a, s_side);
    convh_kernel<<<gch, 256, 0, s_side>>>((const float4*)gp_w, (const float4*)up_w, 1);
    cudaEventRecord(e_b, s_side);
    convd_kernel<<<2048, 256, 0, s_side>>>((const float4*)down_w);
    cudaEventRecord(e_c2, s_side);

    // ---- main line: routing + gather in parallel with conv ----
    init_kernel<<<(out_size + 255) / 256, 256>>>(out, out_size);
    router_kernel<<<NTOK / 8, 256>>>(x, gate_w, gate_b);
    gather_kernel<<<NTOK, 256>>>(x);

    // gemm1 experts 0-3 after first conv half; 4-7 after second
    dim3 g1(26, NTOK / BM, NEXP / 2);
    cudaStreamWaitEvent(0, e_a, 0);
    gemm1_kernel<<<g1, 256, ST1 * 3 * TILE_B>>>(gp_b, up_b, 0);
    cudaStreamWaitEvent(0, e_b, 0);
    gemm1_kernel<<<g1, 256, ST1 * 3 * TILE_B>>>(gp_b, up_b, NEXP / 2);

    cudaStreamWaitEvent(0, e_c2, 0);            // gemm2 needs down16
    dim3 g2(DDIM / 256, NTOK / BM, NEXP);
    gemm2_kernel<<<g2, 256, ST2 * (TILE_B + TILE2B)>>>(down_b, out);
}

// round 17
// speedup vs baseline: 1.0298x; 1.0298x over previous
#include <cuda_runtime.h>
#include <cuda_fp16.h>
#include <math.h>
#include <stdint.h>

#define NTOK 8192
#define DDIM 1024
#define NEXP 8
#define FDIM 3264
#define NROW (NEXP * NTOK)
#define EFD  (NEXP * FDIM * DDIM)

#define BM 128
#define BK 64                          // halves per k-strip
#define SSTR 72                        // smem row stride in halves (conflict-free)
#define TILE_B (128 * SSTR * 2)        // 18432 bytes per 128-row tile
#define TILE2B (256 * SSTR * 2)        // 36864 bytes per 256-row tile
#define ST1 4                          // gemm1 stages (A+G+U = 55296 B/stage)
#define ST2 3                          // gemm2 stages (A+B = 55296 B/stage)

// ---------------- device scratch ----------------
__device__ int    g_counts[NEXP];
__device__ int    g_pos[NTOK * 2];
__device__ int    g_tok[NROW];
__device__ float  g_wts[NROW];
__device__ __half g_Xe[(size_t)NROW * DDIM];
__device__ __half g_H [(size_t)NROW * FDIM];
__device__ __half g_W16[(size_t)3 * EFD];   // [gp | up | down] in fp16

// ---------------- helpers ----------------
__device__ __forceinline__ uint32_t smem_u32(const void* p) {
    uint32_t a;
    asm("{ .reg .u64 t; cvta.to.shared.u64 t, %1; cvt.u32.u64 %0, t; }" : "=r"(a) : "l"(p));
    return a;
}
__device__ __forceinline__ void cp16(uint32_t dst, const void* src, bool valid) {
    uint32_t sz = valid ? 16u : 0u;
    asm volatile("cp.async.cg.shared.global [%0], [%1], 16, %2;"
                 :: "r"(dst), "l"(src), "r"(sz));
}
__device__ __forceinline__ void cp_commit() {
    asm volatile("cp.async.commit_group;" ::: "memory");
}
__device__ __forceinline__ void cp_wait1() {
    asm volatile("cp.async.wait_group 1;" ::: "memory");
}
__device__ __forceinline__ void cp_wait2() {
    asm volatile("cp.async.wait_group 2;" ::: "memory");
}
__device__ __forceinline__ void mma16(float* c, const uint32_t* a, const uint32_t* b) {
    asm("mma.sync.aligned.m16n8k16.row.col.f32.f16.f16.f32 "
        "{%0,%1,%2,%3}, {%4,%5,%6,%7}, {%8,%9}, {%0,%1,%2,%3};"
        : "+f"(c[0]), "+f"(c[1]), "+f"(c[2]), "+f"(c[3])
        : "r"(a[0]), "r"(a[1]), "r"(a[2]), "r"(a[3]), "r"(b[0]), "r"(b[1]));
}
__device__ __forceinline__ void ldsm4(uint32_t* r, uint32_t addr) {
    asm volatile("ldmatrix.sync.aligned.m8n8.x4.shared.b16 {%0,%1,%2,%3}, [%4];"
                 : "=r"(r[0]), "=r"(r[1]), "=r"(r[2]), "=r"(r[3]) : "r"(addr));
}

// ============================================================
// init / conv / router / gather
// ============================================================
__global__ void zero_counts_kernel() {
    if (threadIdx.x < NEXP) g_counts[threadIdx.x] = 0;
}

__global__ __launch_bounds__(256) void zero_out_kernel(float4* __restrict__ out, int n4) {
    int stride = gridDim.x * blockDim.x;
    float4 z = make_float4(0.f, 0.f, 0.f, 0.f);
    for (int i = blockIdx.x * blockDim.x + threadIdx.x; i < n4; i += stride)
        out[i] = z;
}

// converts tensor (ybase + blockIdx.y): 0=gp, 1=up, 2=down
__global__ __launch_bounds__(256) void conv_kernel(const float4* __restrict__ s0,
                                                   const float4* __restrict__ s1,
                                                   const float4* __restrict__ s2,
                                                   int ybase, int n4) {
    int which = ybase + blockIdx.y;
    const float4* src = (which == 0) ? s0 : (which == 1) ? s1 : s2;
    uint2* dst = (uint2*)g_W16 + (size_t)which * n4;
    int stride = gridDim.x * blockDim.x;
    for (int i = blockIdx.x * blockDim.x + threadIdx.x; i < n4; i += stride) {
        float4 v = src[i];
        __half2 h0 = __floats2half2_rn(v.x, v.y);
        __half2 h1 = __floats2half2_rn(v.z, v.w);
        uint2 o;
        o.x = *(const uint32_t*)&h0;
        o.y = *(const uint32_t*)&h1;
        dst[i] = o;
    }
}

__global__ void router_kernel(const float* __restrict__ x,
                              const float* __restrict__ gw,
                              const float* __restrict__ gb) {
    int warp = (blockIdx.x * blockDim.x + threadIdx.x) >> 5;
    int lane = threadIdx.x & 31;
    if (warp >= NTOK) return;
    const float4* xr = (const float4*)(x + (size_t)warp * DDIM);

    float acc[NEXP];
#pragma unroll
    for (int e = 0; e < NEXP; e++) acc[e] = 0.f;
#pragma unroll
    for (int k4 = 0; k4 < DDIM / 4 / 32; k4++) {      // 8 iterations, float4 each
        int k = k4 * 32 + lane;
        float4 xv = xr[k];
#pragma unroll
        for (int e = 0; e < NEXP; e++) {
            float4 wv = ((const float4*)(gw + e * DDIM))[k];
            acc[e] += xv.x * wv.x + xv.y * wv.y + xv.z * wv.z + xv.w * wv.w;
        }
    }
#pragma unroll
    for (int e = 0; e < NEXP; e++)
#pragma unroll
        for (int off = 16; off; off >>= 1)
            acc[e] += __shfl_xor_sync(0xffffffffu, acc[e], off);

    if (lane == 0) {
        float mx = -1e30f;
#pragma unroll
        for (int e = 0; e < NEXP; e++) { acc[e] += gb[e]; mx = fmaxf(mx, acc[e]); }
        float p[NEXP];
#pragma unroll
        for (int e = 0; e < NEXP; e++) p[e] = expf(acc[e] - mx);
        int i1 = 0; float v1 = p[0];
#pragma unroll
        for (int e = 1; e < NEXP; e++) if (p[e] > v1) { v1 = p[e]; i1 = e; }
        int i2 = -1; float v2 = -1.f;
#pragma unroll
        for (int e = 0; e < NEXP; e++) if (e != i1 && p[e] > v2) { v2 = p[e]; i2 = e; }
        float inv = 1.f / (v1 + v2);
        int s1 = atomicAdd(&g_counts[i1], 1);
        int s2 = atomicAdd(&g_counts[i2], 1);
        g_wts[i1 * NTOK + s1] = v1 * inv;
        g_wts[i2 * NTOK + s2] = v2 * inv;
        g_tok[i1 * NTOK + s1] = warp;
        g_tok[i2 * NTOK + s2] = warp;
        g_pos[2 * warp]     = i1 * NTOK + s1;
        g_pos[2 * warp + 1] = i2 * NTOK + s2;
    }
}

__global__ __launch_bounds__(256) void gather_kernel(const float* __restrict__ x) {
    int t  = blockIdx.x;
    int p0 = g_pos[2 * t], p1 = g_pos[2 * t + 1];
    float4 v = ((const float4*)(x + (size_t)t * DDIM))[threadIdx.x];
    __half2 h0 = __floats2half2_rn(v.x, v.y);
    __half2 h1 = __floats2half2_rn(v.z, v.w);
    uint2 o;
    o.x = *(const uint32_t*)&h0;
    o.y = *(const uint32_t*)&h1;
    ((uint2*)(g_Xe + (size_t)p0 * DDIM))[threadIdx.x] = o;
    ((uint2*)(g_Xe + (size_t)p1 * DDIM))[threadIdx.x] = o;
}

// ============================================================
// GEMM1: [128 slot] x [128 f], K=1024, G and U, silu -> g_H (fp16)
// 256 thr, 2x4 warp grid, warp tile 64x32, ldmatrix, 4 stages
// ============================================================
__global__ __launch_bounds__(256, 1) void gemm1_kernel(
    const float* __restrict__ gpb, const float* __restrict__ upb) {

    int e   = blockIdx.z;
    int cnt = g_counts[e];
    int m0  = blockIdx.y * BM;
    if (m0 >= cnt) return;
    int n0  = blockIdx.x * 128;
    int ebase = e * NTOK;

    extern __shared__ __align__(16) __half sh[];
    uint32_t sbase = smem_u32(sh);

    int tid = threadIdx.x;
    int wid = tid >> 5, lane = tid & 31;
    int wr = wid >> 2, wc = wid & 3;        // 2 x 4 warp grid
    int g = lane >> 2, t = lane & 3;

    int rowA = wr * 64 + ((lane >> 3) & 1) * 8 + (lane & 7);
    int colA = ((lane >> 4) & 1) * 8;
    int aoff = rowA * SSTR + colA;
    int rowB = wc * 32 + ((lane >> 4) & 1) * 8 + (lane & 7);
    int colB = ((lane >> 3) & 1) * 8;
    int boff = rowB * SSTR + colB;

    const __half* srcA = g_Xe + (size_t)(ebase + m0) * DDIM;

    float cg[4][4][4], cu[4][4][4];
#pragma unroll
    for (int i = 0; i < 4; i++)
#pragma unroll
        for (int j = 0; j < 4; j++)
#pragma unroll
            for (int r = 0; r < 4; r++) { cg[i][j][r] = 0.f; cu[i][j][r] = 0.f; }

    const int KT = DDIM / BK;               // 16

    auto issue = [&](int kt, int st) {
        int k0 = kt * BK;
        uint32_t sA = sbase + st * (3 * TILE_B);
        uint32_t sG = sA + TILE_B;
        uint32_t sU = sG + TILE_B;
#pragma unroll
        for (int i = 0; i < 4; i++) {
            int c = i * 256 + tid;
            int row = c >> 3, kc = c & 7;
            uint32_t doff = (uint32_t)(row * SSTR + kc * 8) * 2;
            cp16(sA + doff, srcA + (size_t)row * DDIM + k0 + kc * 8, true);
            int nrow = n0 + row;
            bool ok = nrow < FDIM;
            int nr = ok ? nrow : (FDIM - 1);
            size_t woff = ((size_t)e * FDIM + nr) * DDIM + k0 + kc * 8;
            cp16(sG + doff, g_W16 + woff, ok);
            cp16(sU + doff, g_W16 + EFD + woff, ok);
        }
        cp_commit();
    };

#pragma unroll
    for (int s = 0; s < ST1 - 1; s++) issue(s, s);

    for (int kt = 0; kt < KT; kt++) {
        cp_wait2();
        __syncthreads();
        if (kt + ST1 - 1 < KT) issue(kt + ST1 - 1, (kt + ST1 - 1) % ST1);
        else cp_commit();

        int st = kt % ST1;
        uint32_t sA = sbase + st * (3 * TILE_B);
        uint32_t sG = sA + TILE_B;
        uint32_t sU = sG + TILE_B;

#pragma unroll
        for (int kk = 0; kk < 4; kk++) {
            int kb = kk * 16;
            uint32_t a[4][4];
#pragma unroll
            for (int mt = 0; mt < 4; mt++)
                ldsm4(a[mt], sA + (uint32_t)(aoff + mt * 16 * SSTR + kb) * 2);
            uint32_t bg[4][2], bu[4][2];
#pragma unroll
            for (int h = 0; h < 2; h++) {
                uint32_t r[4];
                ldsm4(r, sG + (uint32_t)(boff + h * 16 * SSTR + kb) * 2);
                bg[2*h][0] = r[0]; bg[2*h][1] = r[1];
                bg[2*h+1][0] = r[2]; bg[2*h+1][1] = r[3];
                ldsm4(r, sU + (uint32_t)(boff + h * 16 * SSTR + kb) * 2);
                bu[2*h][0] = r[0]; bu[2*h][1] = r[1];
                bu[2*h+1][0] = r[2]; bu[2*h+1][1] = r[3];
            }
#pragma unroll
            for (int mt = 0; mt < 4; mt++)
#pragma unroll
                for (int nt = 0; nt < 4; nt++) {
                    mma16(cg[mt][nt], a[mt], bg[nt]);
                    mma16(cu[mt][nt], a[mt], bu[nt]);
                }
        }
    }

    // ---- epilogue: silu(g*u) -> g_H (fp16) ----
#pragma unroll
    for (int mt = 0; mt < 4; mt++) {
        int mrow = wr * 64 + mt * 16 + g;
#pragma unroll
        for (int p = 0; p < 2; p++) {
            int slot = m0 + mrow + p * 8;
            bool live = slot < cnt;
            size_t hbase = ((size_t)ebase + slot) * FDIM;
#pragma unroll
            for (int nt = 0; nt < 4; nt++) {
                int col = n0 + wc * 32 + nt * 8 + 2 * t;
                if (live && col < FDIM) {
                    float2 gb = *(const float2*)(gpb + (size_t)e * FDIM + col);
                    float2 ub = *(const float2*)(upb + (size_t)e * FDIM + col);
                    float g0 = cg[mt][nt][2 * p + 0] + gb.x;
                    float g1 = cg[mt][nt][2 * p + 1] + gb.y;
                    float u0 = cu[mt][nt][2 * p + 0] + ub.x;
                    float u1 = cu[mt][nt][2 * p + 1] + ub.y;
                    float z0 = g0 * u0, z1 = g1 * u1;
                    float h0 = z0 / (1.f + expf(-z0));
                    float h1 = z1 / (1.f + expf(-z1));
                    *(__half2*)(g_H + hbase + col) = __floats2half2_rn(h0, h1);
                }
            }
        }
    }
}

// ============================================================
// GEMM2: [128 slot] x [256 d], K=3264 over g_H (fp16),
// 256 thr, 2x4 warp grid, warp tile 64x64, ldmatrix, 3 stages,
// weighted atomicAdd scatter into out
// ============================================================
__global__ __launch_bounds__(256, 1) void gemm2_kernel(
    const float* __restrict__ dwb, float* __restrict__ out) {

    int e   = blockIdx.z;
    int cnt = g_counts[e];
    int m0  = blockIdx.y * BM;
    if (m0 >= cnt) return;
    int n0  = blockIdx.x * 256;
    int ebase = e * NTOK;

    const __half* wd16 = g_W16 + 2 * (size_t)EFD;

    extern __shared__ __align__(16) __half sh[];
    uint32_t sbase = smem_u32(sh);

    int tid = threadIdx.x;
    int wid = tid >> 5, lane = tid & 31;
    int wr = wid >> 2, wc = wid & 3;        // 2 x 4 warp grid, warp tile 64x64
    int g = lane >> 2, t = lane & 3;

    int rowA = wr * 64 + ((lane >> 3) & 1) * 8 + (lane & 7);
    int colA = ((lane >> 4) & 1) * 8;
    int aoff = rowA * SSTR + colA;
    int rowB = wc * 64 + ((lane >> 4) & 1) * 8 + (lane & 7);
    int colB = ((lane >> 3) & 1) * 8;
    int boff = rowB * SSTR + colB;

    const __half* srcA = g_H + (size_t)(ebase + m0) * FDIM;

    float c[4][8][4];
#pragma unroll
    for (int i = 0; i < 4; i++)
#pragma unroll
        for (int j = 0; j < 8; j++)
#pragma unroll
            for (int r = 0; r < 4; r++) c[i][j][r] = 0.f;

    const int KT = FDIM / BK;               // 51
    const int STAGE_B = TILE_B + TILE2B;    // 55296

    auto issue = [&](int kt, int st) {
        int k0 = kt * BK;
        uint32_t sA = sbase + st * STAGE_B;
        uint32_t sB = sA + TILE_B;
#pragma unroll
        for (int i = 0; i < 4; i++) {
            int cc = i * 256 + tid;
            int row = cc >> 3, kc = cc & 7;
            uint32_t doff = (uint32_t)(row * SSTR + kc * 8) * 2;
            cp16(sA + doff, srcA + (size_t)row * FDIM + k0 + kc * 8, true);
        }
#pragma unroll
        for (int j = 0; j < 8; j++) {
            int cc = j * 256 + tid;
            int row = cc >> 3, kc = cc & 7;
            uint32_t doff = (uint32_t)(row * SSTR + kc * 8) * 2;
            cp16(sB + doff, wd16 + ((size_t)e * DDIM + n0 + row) * FDIM + k0 + kc * 8, true);
        }
        cp_commit();
    };

#pragma unroll
    for (int s = 0; s < ST2 - 1; s++) issue(s, s);

    for (int kt = 0; kt < KT; kt++) {
        cp_wait1();
        __syncthreads();
        if (kt + ST2 - 1 < KT) issue(kt + ST2 - 1, (kt + ST2 - 1) % ST2);
        else cp_commit();

        int st = kt % ST2;
        uint32_t sA = sbase + st * STAGE_B;
        uint32_t sB = sA + TILE_B;

#pragma unroll
        for (int kk = 0; kk < 4; kk++) {
            int kb = kk * 16;
            uint32_t a[4][4];
#pragma unroll
            for (int mt = 0; mt < 4; mt++)
                ldsm4(a[mt], sA + (uint32_t)(aoff + mt * 16 * SSTR + kb) * 2);
            uint32_t b[8][2];
#pragma unroll
            for (int h = 0; h < 4; h++) {
                uint32_t r[4];
                ldsm4(r, sB + (uint32_t)(boff + h * 16 * SSTR + kb) * 2);
                b[2*h][0] = r[0]; b[2*h][1] = r[1];
                b[2*h+1][0] = r[2]; b[2*h+1][1] = r[3];
            }
#pragma unroll
            for (int mt = 0; mt < 4; mt++)
#pragma unroll
                for (int nt = 0; nt < 8; nt++)
                    mma16(c[mt][nt], a[mt], b[nt]);
        }
    }

    // ---- epilogue: (c + bias) * w, atomicAdd scatter ----
#pragma unroll
    for (int mt = 0; mt < 4; mt++) {
        int mrow = wr * 64 + mt * 16 + g;
#pragma unroll
        for (int p = 0; p < 2; p++) {
            int slot = m0 + mrow + p * 8;
            if (slot >= cnt) continue;
            float w   = g_wts[ebase + slot];
            int   tok = g_tok[ebase + slot];
            float* orow = out + (size_t)tok * DDIM;
#pragma unroll
            for (int nt = 0; nt < 8; nt++) {
                int col = n0 + wc * 64 + nt * 8 + 2 * t;
                float2 db = *(const float2*)(dwb + (size_t)e * DDIM + col);
                float y0 = (c[mt][nt][2 * p + 0] + db.x) * w;
                float y1 = (c[mt][nt][2 * p + 1] + db.y) * w;
                atomicAdd(orow + col, y0);
                atomicAdd(orow + col + 1, y1);
            }
        }
    }
}

// ============================================================
extern "C" void kernel_launch(void* const* d_in, const int* in_sizes, int n_in,
                              void* d_out, int out_size) {
    const float* x      = (const float*)d_in[0];
    const float* gate_w = (const float*)d_in[1];
    const float* gate_b = (const float*)d_in[2];
    const float* up_w   = (const float*)d_in[3];
    const float* up_b   = (const float*)d_in[4];
    const float* gp_w   = (const float*)d_in[5];
    const float* gp_b   = (const float*)d_in[6];
    const float* down_w = (const float*)d_in[7];
    const float* down_b = (const float*)d_in[8];
    float* out = (float*)d_out;
    (void)in_sizes; (void)n_in;

    // one-time host-side setup (no device allocations)
    static cudaStream_t s_side = nullptr;
    static cudaEvent_t e_fork = nullptr, e_c1 = nullptr, e_c2 = nullptr;
    if (!s_side) {
        cudaStreamCreateWithFlags(&s_side, cudaStreamNonBlocking);
        cudaEventCreateWithFlags(&e_fork, cudaEventDisableTiming);
        cudaEventCreateWithFlags(&e_c1,   cudaEventDisableTiming);
        cudaEventCreateWithFlags(&e_c2,   cudaEventDisableTiming);
        cudaFuncSetAttribute(gemm1_kernel, cudaFuncAttributeMaxDynamicSharedMemorySize,
                             ST1 * 3 * TILE_B);
        cudaFuncSetAttribute(gemm2_kernel, cudaFuncAttributeMaxDynamicSharedMemorySize,
                             ST2 * (TILE_B + TILE2B));
    }

    // ---- fork: side stream does weight conversion + out zeroing ----
    cudaEventRecord(e_fork, 0);
    cudaStreamWaitEvent(s_side, e_fork, 0);

    dim3 gc1(2048, 2);     // gp + up
    conv_kernel<<<gc1, 256, 0, s_side>>>((const float4*)gp_w, (const float4*)up_w,
                                         (const float4*)down_w, 0, EFD / 4);
    cudaEventRecord(e_c1, s_side);

    dim3 gc2(2048, 1);     // down (overlaps with gemm1)
    conv_kernel<<<gc2, 256, 0, s_side>>>((const float4*)gp_w, (const float4*)up_w,
                                         (const float4*)down_w, 2, EFD / 4);
    zero_out_kernel<<<1184, 256, 0, s_side>>>((float4*)out, out_size / 4);
    cudaEventRecord(e_c2, s_side);

    // ---- main line: routing + gather in parallel with conv1 ----
    zero_counts_kernel<<<1, 32>>>();
    router_kernel<<<NTOK / 8, 256>>>(x, gate_w, gate_b);
    gather_kernel<<<NTOK, 256>>>(x);

    cudaStreamWaitEvent(0, e_c1, 0);            // gemm1 needs gp16/up16
    dim3 g1(26, NTOK / BM, NEXP);
    gemm1_kernel<<<g1, 256, ST1 * 3 * TILE_B>>>(gp_b, up_b);

    cudaStreamWaitEvent(0, e_c2, 0);            // gemm2 needs down16 + zeroed out
    dim3 g2(DDIM / 256, NTOK / BM, NEXP);
    gemm2_kernel<<<g2, 256, ST2 * (TILE_B + TILE2B)>>>(down_b, out);
}